// round 11
// baseline (speedup 1.0000x reference)
#include <cuda_runtime.h>
#include <math.h>
#include <stdint.h>
#include <mma.h>

using namespace nvcuda;

#define BATCH   2
#define SEQ     2048
#define NTOK    (BATCH*SEQ)      /* 4096 */
#define DIM     768
#define DINNER  1536
#define DSTATE  16
#define DCONV   4
#define DTRANK  48
#define DBLW    80               /* DT_RANK + 2*D_STATE */
#define VOCAB   32000
#define DEPTH   4
#define EPS     1e-5f

typedef unsigned long long u64;

// ---------------------------------------------------------------------------
// Static device scratch (no allocations allowed)
// ---------------------------------------------------------------------------
__device__ __align__(16) float g_x   [NTOK*DIM];
__device__ __align__(16) float g_xz  [NTOK*2*DINNER];
__device__ __align__(16) float g_xssm[NTOK*DINNER];
__device__ __align__(16) float g_dbl [NTOK*DBLW];
__device__ __align__(16) float g_dt  [NTOK*DINNER];
__device__ __align__(16) float g_gate[NTOK*DINNER];
__device__ __align__(16) float g_ln  [NTOK*DIM];

// ---------------------------------------------------------------------------
// Packed-f32x2 helpers (SIMT GEMM path)
// ---------------------------------------------------------------------------
__device__ __forceinline__ u64 dup2(float x) {
    u64 r; asm("mov.b64 %0, {%1, %1};" : "=l"(r) : "f"(x)); return r;
}
__device__ __forceinline__ float2 unpack2(u64 v) {
    float2 r; asm("mov.b64 {%0, %1}, %2;" : "=f"(r.x), "=f"(r.y) : "l"(v)); return r;
}
__device__ __forceinline__ u64 ffma2(u64 a, u64 b, u64 c) {
    u64 d; asm("fma.rn.f32x2 %0, %1, %2, %3;" : "=l"(d) : "l"(a), "l"(b), "l"(c)); return d;
}

// FMA-pipe-only exp: 2^(x*log2e), magic-number split + degree-5 poly.
__device__ __forceinline__ float fexp(float x) {
    x = fmaxf(x, -87.0f);
    float t = x * 1.4426950408889634f;
    float r = t + 12582912.0f;
    float f = t - (r - 12582912.0f);
    float p = 1.3333558e-3f;
    p = fmaf(p, f, 9.6181291e-3f);
    p = fmaf(p, f, 5.5504109e-2f);
    p = fmaf(p, f, 2.4022651e-1f);
    p = fmaf(p, f, 6.9314718e-1f);
    p = fmaf(p, f, 1.0f);
    return __int_as_float(__float_as_int(p) + (__float_as_int(r) << 23));
}
__device__ __forceinline__ float softplusf(float v) {
    return v > 20.f ? v : log1pf(__expf(v));
}
__device__ __forceinline__ float siluf(float v) {
    return v * (1.f / (1.f + __expf(-v)));
}

// ---------------------------------------------------------------------------
// Tensor-core GEMM via wmma tf32 (legacy HMMA path — valid on .target sm_103).
// C[M,N] = A[M,K] @ W[N,K]^T.  M%128==0, N%128==0, K%32==0.
// Block tile 128x128x32; 8 warps in 4(m) x 2(n); warp tile 32x64 = 2x4 frags.
// ---------------------------------------------------------------------------
#define GW_PAD 4
#define GW_LDS (32 + GW_PAD)

__device__ __forceinline__ void gw_ldg(float4* r, const float* base, int ld,
                                       int row0, int k0, int tid) {
#pragma unroll
    for (int p = 0; p < 4; p++) {
        int idx = tid + (p << 8);
        int row = idx >> 3;
        int c4  = (idx & 7) << 2;
        r[p] = *(const float4*)(base + (size_t)(row0 + row) * ld + k0 + c4);
    }
}
__device__ __forceinline__ void gw_sts(float* S, const float4* r, int tid) {
#pragma unroll
    for (int p = 0; p < 4; p++) {
        int idx = tid + (p << 8);
        int row = idx >> 3;
        int c4  = (idx & 7) << 2;
        float4 v = r[p];
        v.x = wmma::__float_to_tf32(v.x);
        v.y = wmma::__float_to_tf32(v.y);
        v.z = wmma::__float_to_tf32(v.z);
        v.w = wmma::__float_to_tf32(v.w);
        *(float4*)(S + row * GW_LDS + c4) = v;
    }
}

__global__ void __launch_bounds__(256) gemm_wmma(
    const float* __restrict__ A, int lda,
    const float* __restrict__ W, int ldw,
    float* __restrict__ C, int ldc, int K)
{
    __shared__ __align__(16) float As[128 * GW_LDS];
    __shared__ __align__(16) float Ws[128 * GW_LDS];

    const int tid = threadIdx.x;
    const int wid = tid >> 5;
    const int m0 = blockIdx.y * 128;
    const int n0 = blockIdx.x * 128;
    const int wm = wid & 3;          // 4 m-slots of 32 rows
    const int wn = wid >> 2;         // 2 n-slots of 64 cols

    wmma::fragment<wmma::accumulator, 16, 16, 8, float> acc[2][4];
#pragma unroll
    for (int mt = 0; mt < 2; mt++)
#pragma unroll
        for (int nt = 0; nt < 4; nt++)
            wmma::fill_fragment(acc[mt][nt], 0.0f);

    float4 ra[4], rb[4];
    gw_ldg(ra, A, lda, m0, 0, tid);
    gw_ldg(rb, W, ldw, n0, 0, tid);

    for (int k0 = 0; k0 < K; k0 += 32) {
        gw_sts(As, ra, tid);
        gw_sts(Ws, rb, tid);
        __syncthreads();

        if (k0 + 32 < K) {                    // prefetch next global tile
            gw_ldg(ra, A, lda, m0, k0 + 32, tid);
            gw_ldg(rb, W, ldw, n0, k0 + 32, tid);
        }

#pragma unroll
        for (int ks = 0; ks < 4; ks++) {
            wmma::fragment<wmma::matrix_a, 16, 16, 8,
                           wmma::precision::tf32, wmma::row_major> af[2];
            wmma::fragment<wmma::matrix_b, 16, 16, 8,
                           wmma::precision::tf32, wmma::col_major> bf[4];
#pragma unroll
            for (int mt = 0; mt < 2; mt++)
                wmma::load_matrix_sync(af[mt],
                    As + (wm * 32 + mt * 16) * GW_LDS + ks * 8, GW_LDS);
#pragma unroll
            for (int nt = 0; nt < 4; nt++)
                wmma::load_matrix_sync(bf[nt],
                    Ws + (wn * 64 + nt * 16) * GW_LDS + ks * 8, GW_LDS);
#pragma unroll
            for (int mt = 0; mt < 2; mt++)
#pragma unroll
                for (int nt = 0; nt < 4; nt++)
                    wmma::mma_sync(acc[mt][nt], af[mt], bf[nt], acc[mt][nt]);
        }
        __syncthreads();
    }

#pragma unroll
    for (int mt = 0; mt < 2; mt++)
#pragma unroll
        for (int nt = 0; nt < 4; nt++)
            wmma::store_matrix_sync(
                C + (size_t)(m0 + wm * 32 + mt * 16) * ldc
                  + n0 + wn * 64 + nt * 16,
                acc[mt][nt], ldc, wmma::mem_row_major);
}

// ---------------------------------------------------------------------------
// Embedding gather
// ---------------------------------------------------------------------------
__global__ void embed_kernel(const int* __restrict__ ids,
                             const float* __restrict__ emb) {
    int row = blockIdx.x;
    int id  = ids[row];
    const float4* src = (const float4*)(emb + (size_t)id * DIM);
    float4* dst = (float4*)(g_x + (size_t)row * DIM);
    dst[threadIdx.x] = src[threadIdx.x];
}

// ---------------------------------------------------------------------------
// SIMT FFMA2 GEMM (ragged shapes: W_x N=80, W_dt K=48)
// ---------------------------------------------------------------------------
template<int EPI>
__global__ void __launch_bounds__(256, 2) gemm_nt(
    const float* __restrict__ A, int lda,
    const float* __restrict__ W, int ldw,
    const float* __restrict__ bias,
    float* __restrict__ C, int ldc,
    int N, int K)
{
    constexpr int BM = 128, BN = 128, BK = 16, TM = 8, TN = 8;
    constexpr int TX = BN / TN;
    constexpr int KV = BK / 4;
    constexpr int AROWS = 256 / KV;
    constexpr int AV = BM / AROWS;
    constexpr int WV = BN / AROWS;

    __shared__ __align__(16) float As[BK][BM];
    __shared__ __align__(16) float Ws[BK][BN];

    const int tid = threadIdx.x;
    const int m0 = blockIdx.y * BM;
    const int n0 = blockIdx.x * BN;
    const int ar = tid / KV;
    const int ak = (tid % KV) * 4;

    const float* Ag = A + (size_t)(m0 + ar) * lda + ak;
    const float* Wg = W + (size_t)(n0 + ar) * ldw + ak;

    float4 pa[AV], pw[WV];
#pragma unroll
    for (int p = 0; p < AV; p++)
        pa[p] = *(const float4*)(Ag + (size_t)p * AROWS * lda);
#pragma unroll
    for (int p = 0; p < WV; p++)
        pw[p] = (n0 + ar + p * AROWS < N)
              ? *(const float4*)(Wg + (size_t)p * AROWS * ldw)
              : make_float4(0.f, 0.f, 0.f, 0.f);

    u64 acc[TM][TN/2];
#pragma unroll
    for (int i = 0; i < TM; i++)
#pragma unroll
        for (int j = 0; j < TN/2; j++) acc[i][j] = 0ull;

    const int tx = tid % TX;
    const int ty = tid / TX;

    for (int k0 = 0; k0 < K; k0 += BK) {
#pragma unroll
        for (int p = 0; p < AV; p++) {
            int r = ar + p * AROWS;
            As[ak+0][r] = pa[p].x; As[ak+1][r] = pa[p].y;
            As[ak+2][r] = pa[p].z; As[ak+3][r] = pa[p].w;
        }
#pragma unroll
        for (int p = 0; p < WV; p++) {
            int r = ar + p * AROWS;
            Ws[ak+0][r] = pw[p].x; Ws[ak+1][r] = pw[p].y;
            Ws[ak+2][r] = pw[p].z; Ws[ak+3][r] = pw[p].w;
        }
        __syncthreads();

        if (k0 + BK < K) {
#pragma unroll
            for (int p = 0; p < AV; p++)
                pa[p] = *(const float4*)(Ag + (k0 + BK) + (size_t)p * AROWS * lda);
#pragma unroll
            for (int p = 0; p < WV; p++)
                pw[p] = (n0 + ar + p * AROWS < N)
                      ? *(const float4*)(Wg + (k0 + BK) + (size_t)p * AROWS * ldw)
                      : make_float4(0.f, 0.f, 0.f, 0.f);
        }

#pragma unroll
        for (int k = 0; k < BK; k++) {
            float a[TM];
#pragma unroll
            for (int i = 0; i < TM; i += 4)
                *(float4*)(a + i) = *(const float4*)(&As[k][ty * TM + i]);
            u64 w2[TN/2];
#pragma unroll
            for (int j = 0; j < TN; j += 4) {
                ulonglong2 wv = *(const ulonglong2*)(&Ws[k][tx * TN + j]);
                w2[j/2] = wv.x; w2[j/2 + 1] = wv.y;
            }
#pragma unroll
            for (int i = 0; i < TM; i++) {
                u64 ad = dup2(a[i]);
#pragma unroll
                for (int j = 0; j < TN/2; j++)
                    acc[i][j] = ffma2(ad, w2[j], acc[i][j]);
            }
        }
        __syncthreads();
    }

#pragma unroll
    for (int i = 0; i < TM; i++) {
        float* crow = C + (size_t)(m0 + ty * TM + i) * ldc;
#pragma unroll
        for (int j = 0; j < TN; j += 4) {
            int n = n0 + tx * TN + j;
            if (n + 3 < N) {
                float2 p0 = unpack2(acc[i][j/2]);
                float2 p1 = unpack2(acc[i][j/2 + 1]);
                float4 v = make_float4(p0.x, p0.y, p1.x, p1.y);
                if (EPI == 1) {
                    v.x = softplusf(v.x + bias[n+0]);
                    v.y = softplusf(v.y + bias[n+1]);
                    v.z = softplusf(v.z + bias[n+2]);
                    v.w = softplusf(v.w + bias[n+3]);
                }
                *(float4*)(crow + n) = v;
            }
        }
    }
}

// ---------------------------------------------------------------------------
// Causal depthwise conv (width 4) + SiLU
// ---------------------------------------------------------------------------
__global__ void conv_silu_kernel(const float* __restrict__ cw,
                                 const float* __restrict__ cb) {
    int idx = blockIdx.x * blockDim.x + threadIdx.x;
    if (idx >= NTOK * DINNER) return;
    int ch = idx % DINNER;
    int t  = idx / DINNER;
    int l  = t % SEQ;
    float acc = cb[ch];
#pragma unroll
    for (int k = 0; k < DCONV; k++) {
        int dl = l + k - (DCONV - 1);
        if (dl >= 0)
            acc = fmaf(g_xz[(size_t)(t + k - (DCONV - 1)) * (2*DINNER) + ch],
                       cw[ch * DCONV + k], acc);
    }
    g_xssm[idx] = siluf(acc);
}

// ---------------------------------------------------------------------------
// Selective scan: 4 threads/channel, 4 states each, shfl-reduce y
// ---------------------------------------------------------------------------
__global__ void scan_kernel(const float* __restrict__ A_log_l,
                            const float* __restrict__ Dp_l) {
    int lane = threadIdx.x;
    int gch = blockIdx.x * 16 + (lane >> 2);
    int sg  = lane & 3;
    int b   = gch / DINNER;
    int ch  = gch - b * DINNER;
    int s0  = sg * 4;

    float A0 = -__expf(A_log_l[ch * DSTATE + s0 + 0]);
    float A1 = -__expf(A_log_l[ch * DSTATE + s0 + 1]);
    float A2 = -__expf(A_log_l[ch * DSTATE + s0 + 2]);
    float A3 = -__expf(A_log_l[ch * DSTATE + s0 + 3]);
    float Dpc = Dp_l[ch];

    const float* dtp = g_dt   + (size_t)b * SEQ * DINNER + ch;
    const float* xp  = g_xssm + (size_t)b * SEQ * DINNER + ch;
    const float* blp = g_dbl  + (size_t)b * SEQ * DBLW + DTRANK + s0;
    float*       gp  = g_gate + (size_t)b * SEQ * DINNER + ch;

    float h0 = 0.f, h1 = 0.f, h2 = 0.f, h3 = 0.f;
    float dtv = *dtp, xv = *xp;
    float4 Bv = *(const float4*)blp;
    float4 Cv = *(const float4*)(blp + DSTATE);

    for (int t = 0; t < SEQ; t++) {
        bool more = (t + 1 < SEQ);
        float ndt = more ? dtp[DINNER] : 0.f;
        float nxv = more ? xp[DINNER]  : 0.f;
        float4 nB = more ? *(const float4*)(blp + DBLW)          : make_float4(0,0,0,0);
        float4 nC = more ? *(const float4*)(blp + DBLW + DSTATE) : make_float4(0,0,0,0);

        float dx = dtv * xv;
        float e0 = fexp(dtv * A0);
        float e1 = fexp(dtv * A1);
        float e2 = fexp(dtv * A2);
        float e3 = fexp(dtv * A3);
        h0 = fmaf(h0, e0, dx * Bv.x);
        h1 = fmaf(h1, e1, dx * Bv.y);
        h2 = fmaf(h2, e2, dx * Bv.z);
        h3 = fmaf(h3, e3, dx * Bv.w);
        float y = fmaf(h0, Cv.x, fmaf(h1, Cv.y, fmaf(h2, Cv.z, h3 * Cv.w)));
        y += __shfl_xor_sync(0xffffffffu, y, 1);
        y += __shfl_xor_sync(0xffffffffu, y, 2);
        if (sg == 0) *gp = fmaf(xv, Dpc, y);

        dtv = ndt; xv = nxv; Bv = nB; Cv = nC;
        dtp += DINNER; xp += DINNER; blp += DBLW; gp += DINNER;
    }
}

__global__ void gate_kernel() {
    int idx = blockIdx.x * blockDim.x + threadIdx.x;
    if (idx >= NTOK * DINNER) return;
    int ch = idx % DINNER;
    int t  = idx / DINNER;
    float z = g_xz[(size_t)t * (2*DINNER) + DINNER + ch];
    g_gate[idx] *= siluf(z);
}

__global__ void ln_kernel(const float* __restrict__ gw,
                          const float* __restrict__ bw) {
    __shared__ float red[64];
    int row = blockIdx.x;
    const float* xr = g_x + (size_t)row * DIM;
    float s = 0.f, s2 = 0.f;
    for (int i = threadIdx.x; i < DIM; i += blockDim.x) {
        float v = xr[i]; s += v; s2 = fmaf(v, v, s2);
    }
#pragma unroll
    for (int off = 16; off; off >>= 1) {
        s  += __shfl_xor_sync(0xffffffffu, s,  off);
        s2 += __shfl_xor_sync(0xffffffffu, s2, off);
    }
    int w = threadIdx.x >> 5;
    if ((threadIdx.x & 31) == 0) { red[w] = s; red[w + 32] = s2; }
    __syncthreads();
    if (threadIdx.x < 32) {
        int nw = blockDim.x >> 5;
        s  = (threadIdx.x < nw) ? red[threadIdx.x]      : 0.f;
        s2 = (threadIdx.x < nw) ? red[threadIdx.x + 32] : 0.f;
#pragma unroll
        for (int off = 4; off; off >>= 1) {
            s  += __shfl_xor_sync(0xffffffffu, s,  off);
            s2 += __shfl_xor_sync(0xffffffffu, s2, off);
        }
        if (threadIdx.x == 0) { red[0] = s; red[1] = s2; }
    }
    __syncthreads();
    float mu  = red[0] * (1.f / DIM);
    float var = red[1] * (1.f / DIM) - mu * mu;
    float rs  = rsqrtf(var + EPS);
    for (int i = threadIdx.x; i < DIM; i += blockDim.x)
        g_ln[(size_t)row * DIM + i] = (xr[i] - mu) * rs * gw[i] + bw[i];
}

// ---------------------------------------------------------------------------
// Launch sequence
// ---------------------------------------------------------------------------
extern "C" void kernel_launch(void* const* d_in, const int* in_sizes, int n_in,
                              void* d_out, int out_size) {
    (void)in_sizes; (void)n_in; (void)out_size;

    const int*   ids    = (const int*)  d_in[0];
    const float* emb    = (const float*)d_in[1];
    const float* W_in   = (const float*)d_in[2];
    const float* conv_w = (const float*)d_in[3];
    const float* conv_b = (const float*)d_in[4];
    const float* W_x    = (const float*)d_in[5];
    const float* W_dt   = (const float*)d_in[6];
    const float* b_dt   = (const float*)d_in[7];
    const float* A_log  = (const float*)d_in[8];
    const float* Dp     = (const float*)d_in[9];
    const float* W_out  = (const float*)d_in[10];
    const float* ln_g   = (const float*)d_in[11];
    const float* ln_b   = (const float*)d_in[12];
    const float* W_head = (const float*)d_in[13];
    float* out = (float*)d_out;

    float *px, *pxz, *pxssm, *pdbl, *pdt, *pgate, *pln;
    cudaGetSymbolAddress((void**)&px,    g_x);
    cudaGetSymbolAddress((void**)&pxz,   g_xz);
    cudaGetSymbolAddress((void**)&pxssm, g_xssm);
    cudaGetSymbolAddress((void**)&pdbl,  g_dbl);
    cudaGetSymbolAddress((void**)&pdt,   g_dt);
    cudaGetSymbolAddress((void**)&pgate, g_gate);
    cudaGetSymbolAddress((void**)&pln,   g_ln);

    embed_kernel<<<NTOK, DIM/4>>>(ids, emb);

    const int EW = (NTOK * DINNER + 255) / 256;

    for (int i = 0; i < DEPTH; i++) {
        const float* Wi  = W_in   + (size_t)i * 2*DINNER*DIM;
        const float* cwi = conv_w + (size_t)i * DINNER*DCONV;
        const float* cbi = conv_b + (size_t)i * DINNER;
        const float* Wxi = W_x    + (size_t)i * DBLW*DINNER;
        const float* Wdi = W_dt   + (size_t)i * DINNER*DTRANK;
        const float* bdi = b_dt   + (size_t)i * DINNER;
        const float* Ali = A_log  + (size_t)i * DINNER*DSTATE;
        const float* Dpi = Dp     + (size_t)i * DINNER;
        const float* Woi = W_out  + (size_t)i * DIM*DINNER;

        // xz = x @ W_in^T : [4096, 3072]  (tensor core tf32)
        gemm_wmma<<<dim3(2*DINNER/128, NTOK/128), 256>>>(
            px, DIM, Wi, DIM, pxz, 2*DINNER, DIM);

        conv_silu_kernel<<<EW, 256>>>(cwi, cbi);

        // dbl = x_ssm @ W_x^T : [4096, 80]  (SIMT, ragged N)
        gemm_nt<0><<<dim3(1, NTOK/128), 256>>>(
            pxssm, DINNER, Wxi, DINNER, nullptr, pdbl, DBLW, DBLW, DINNER);

        // dt = softplus(dbl[:, :48] @ W_dt^T + b_dt)  (SIMT, K=48)
        gemm_nt<1><<<dim3(DINNER/128, NTOK/128), 256>>>(
            pdbl, DBLW, Wdi, DTRANK, bdi, pdt, DINNER, DINNER, DTRANK);

        scan_kernel<<<(BATCH*DINNER)/16, 64>>>(Ali, Dpi);

        gate_kernel<<<EW, 256>>>();

        // x = g @ W_out^T : [4096, 768]  (tensor core tf32)
        gemm_wmma<<<dim3(DIM/128, NTOK/128), 256>>>(
            pgate, DINNER, Woi, DINNER, px, DIM, DINNER);
    }

    ln_kernel<<<NTOK, 256>>>(ln_g, ln_b);

    // logits = ln @ W_head^T : [4096, 32000]  (tensor core tf32)
    gemm_wmma<<<dim3(VOCAB/128, NTOK/128), 256>>>(
        pln, DIM, W_head, DIM, out, VOCAB, DIM);
}

// round 12
// speedup vs baseline: 1.0217x; 1.0217x over previous
#include <cuda_runtime.h>
#include <math.h>
#include <stdint.h>
#include <mma.h>

using namespace nvcuda;

#define BATCH   2
#define SEQ     2048
#define NTOK    (BATCH*SEQ)      /* 4096 */
#define DIM     768
#define DINNER  1536
#define DSTATE  16
#define DCONV   4
#define DTRANK  48
#define DBLW    80               /* DT_RANK + 2*D_STATE */
#define VOCAB   32000
#define DEPTH   4
#define EPS     1e-5f

typedef unsigned long long u64;

// ---------------------------------------------------------------------------
// Static device scratch (no allocations allowed)
// ---------------------------------------------------------------------------
__device__ __align__(16) float g_x   [NTOK*DIM];
__device__ __align__(16) float g_xz  [NTOK*2*DINNER];
__device__ __align__(16) float g_xssm[NTOK*DINNER];
__device__ __align__(16) float g_dbl [NTOK*DBLW];
__device__ __align__(16) float g_dt  [NTOK*DINNER];
__device__ __align__(16) float g_gate[NTOK*DINNER];
__device__ __align__(16) float g_ln  [NTOK*DIM];

// ---------------------------------------------------------------------------
// Packed-f32x2 helpers (SIMT GEMM path)
// ---------------------------------------------------------------------------
__device__ __forceinline__ u64 dup2(float x) {
    u64 r; asm("mov.b64 %0, {%1, %1};" : "=l"(r) : "f"(x)); return r;
}
__device__ __forceinline__ float2 unpack2(u64 v) {
    float2 r; asm("mov.b64 {%0, %1}, %2;" : "=f"(r.x), "=f"(r.y) : "l"(v)); return r;
}
__device__ __forceinline__ u64 ffma2(u64 a, u64 b, u64 c) {
    u64 d; asm("fma.rn.f32x2 %0, %1, %2, %3;" : "=l"(d) : "l"(a), "l"(b), "l"(c)); return d;
}

// FMA-pipe-only exp: 2^(x*log2e), magic-number split + degree-5 poly.
__device__ __forceinline__ float fexp(float x) {
    x = fmaxf(x, -87.0f);
    float t = x * 1.4426950408889634f;
    float r = t + 12582912.0f;
    float f = t - (r - 12582912.0f);
    float p = 1.3333558e-3f;
    p = fmaf(p, f, 9.6181291e-3f);
    p = fmaf(p, f, 5.5504109e-2f);
    p = fmaf(p, f, 2.4022651e-1f);
    p = fmaf(p, f, 6.9314718e-1f);
    p = fmaf(p, f, 1.0f);
    return __int_as_float(__float_as_int(p) + (__float_as_int(r) << 23));
}
__device__ __forceinline__ float softplusf(float v) {
    return v > 20.f ? v : log1pf(__expf(v));
}
__device__ __forceinline__ float siluf(float v) {
    return v * (1.f / (1.f + __expf(-v)));
}

// ---------------------------------------------------------------------------
// Tensor-core GEMM via wmma tf32 (legacy HMMA path — valid on .target sm_103).
// C[M,N] = A[M,K] @ W[N,K]^T.  M%128==0, N%128==0, K%32==0.
// Block tile 128x128x32; 8 warps in 4(m) x 2(n); warp tile 32x64 = 2x4 frags.
// ---------------------------------------------------------------------------
#define GW_PAD 4
#define GW_LDS (32 + GW_PAD)

__device__ __forceinline__ void gw_ldg(float4* r, const float* base, int ld,
                                       int row0, int k0, int tid) {
#pragma unroll
    for (int p = 0; p < 4; p++) {
        int idx = tid + (p << 8);
        int row = idx >> 3;
        int c4  = (idx & 7) << 2;
        r[p] = *(const float4*)(base + (size_t)(row0 + row) * ld + k0 + c4);
    }
}
__device__ __forceinline__ void gw_sts(float* S, const float4* r, int tid) {
#pragma unroll
    for (int p = 0; p < 4; p++) {
        int idx = tid + (p << 8);
        int row = idx >> 3;
        int c4  = (idx & 7) << 2;
        float4 v = r[p];
        v.x = wmma::__float_to_tf32(v.x);
        v.y = wmma::__float_to_tf32(v.y);
        v.z = wmma::__float_to_tf32(v.z);
        v.w = wmma::__float_to_tf32(v.w);
        *(float4*)(S + row * GW_LDS + c4) = v;
    }
}

__global__ void __launch_bounds__(256) gemm_wmma(
    const float* __restrict__ A, int lda,
    const float* __restrict__ W, int ldw,
    float* __restrict__ C, int ldc, int K)
{
    __shared__ __align__(16) float As[128 * GW_LDS];
    __shared__ __align__(16) float Ws[128 * GW_LDS];

    const int tid = threadIdx.x;
    const int wid = tid >> 5;
    const int m0 = blockIdx.y * 128;
    const int n0 = blockIdx.x * 128;
    const int wm = wid & 3;          // 4 m-slots of 32 rows
    const int wn = wid >> 2;         // 2 n-slots of 64 cols

    wmma::fragment<wmma::accumulator, 16, 16, 8, float> acc[2][4];
#pragma unroll
    for (int mt = 0; mt < 2; mt++)
#pragma unroll
        for (int nt = 0; nt < 4; nt++)
            wmma::fill_fragment(acc[mt][nt], 0.0f);

    float4 ra[4], rb[4];
    gw_ldg(ra, A, lda, m0, 0, tid);
    gw_ldg(rb, W, ldw, n0, 0, tid);

    for (int k0 = 0; k0 < K; k0 += 32) {
        gw_sts(As, ra, tid);
        gw_sts(Ws, rb, tid);
        __syncthreads();

        if (k0 + 32 < K) {                    // prefetch next global tile
            gw_ldg(ra, A, lda, m0, k0 + 32, tid);
            gw_ldg(rb, W, ldw, n0, k0 + 32, tid);
        }

#pragma unroll
        for (int ks = 0; ks < 4; ks++) {
            wmma::fragment<wmma::matrix_a, 16, 16, 8,
                           wmma::precision::tf32, wmma::row_major> af[2];
            wmma::fragment<wmma::matrix_b, 16, 16, 8,
                           wmma::precision::tf32, wmma::col_major> bf[4];
#pragma unroll
            for (int mt = 0; mt < 2; mt++)
                wmma::load_matrix_sync(af[mt],
                    As + (wm * 32 + mt * 16) * GW_LDS + ks * 8, GW_LDS);
#pragma unroll
            for (int nt = 0; nt < 4; nt++)
                wmma::load_matrix_sync(bf[nt],
                    Ws + (wn * 64 + nt * 16) * GW_LDS + ks * 8, GW_LDS);
#pragma unroll
            for (int mt = 0; mt < 2; mt++)
#pragma unroll
                for (int nt = 0; nt < 4; nt++)
                    wmma::mma_sync(acc[mt][nt], af[mt], bf[nt], acc[mt][nt]);
        }
        __syncthreads();
    }

#pragma unroll
    for (int mt = 0; mt < 2; mt++)
#pragma unroll
        for (int nt = 0; nt < 4; nt++)
            wmma::store_matrix_sync(
                C + (size_t)(m0 + wm * 32 + mt * 16) * ldc
                  + n0 + wn * 64 + nt * 16,
                acc[mt][nt], ldc, wmma::mem_row_major);
}

// ---------------------------------------------------------------------------
// Embedding gather
// ---------------------------------------------------------------------------
__global__ void embed_kernel(const int* __restrict__ ids,
                             const float* __restrict__ emb) {
    int row = blockIdx.x;
    int id  = ids[row];
    const float4* src = (const float4*)(emb + (size_t)id * DIM);
    float4* dst = (float4*)(g_x + (size_t)row * DIM);
    dst[threadIdx.x] = src[threadIdx.x];
}

// ---------------------------------------------------------------------------
// SIMT FFMA2 GEMM (ragged shapes: W_x N=80, W_dt K=48)
// ---------------------------------------------------------------------------
template<int EPI>
__global__ void __launch_bounds__(256, 2) gemm_nt(
    const float* __restrict__ A, int lda,
    const float* __restrict__ W, int ldw,
    const float* __restrict__ bias,
    float* __restrict__ C, int ldc,
    int N, int K)
{
    constexpr int BM = 128, BN = 128, BK = 16, TM = 8, TN = 8;
    constexpr int TX = BN / TN;
    constexpr int KV = BK / 4;
    constexpr int AROWS = 256 / KV;
    constexpr int AV = BM / AROWS;
    constexpr int WV = BN / AROWS;

    __shared__ __align__(16) float As[BK][BM];
    __shared__ __align__(16) float Ws[BK][BN];

    const int tid = threadIdx.x;
    const int m0 = blockIdx.y * BM;
    const int n0 = blockIdx.x * BN;
    const int ar = tid / KV;
    const int ak = (tid % KV) * 4;

    const float* Ag = A + (size_t)(m0 + ar) * lda + ak;
    const float* Wg = W + (size_t)(n0 + ar) * ldw + ak;

    float4 pa[AV], pw[WV];
#pragma unroll
    for (int p = 0; p < AV; p++)
        pa[p] = *(const float4*)(Ag + (size_t)p * AROWS * lda);
#pragma unroll
    for (int p = 0; p < WV; p++)
        pw[p] = (n0 + ar + p * AROWS < N)
              ? *(const float4*)(Wg + (size_t)p * AROWS * ldw)
              : make_float4(0.f, 0.f, 0.f, 0.f);

    u64 acc[TM][TN/2];
#pragma unroll
    for (int i = 0; i < TM; i++)
#pragma unroll
        for (int j = 0; j < TN/2; j++) acc[i][j] = 0ull;

    const int tx = tid % TX;
    const int ty = tid / TX;

    for (int k0 = 0; k0 < K; k0 += BK) {
#pragma unroll
        for (int p = 0; p < AV; p++) {
            int r = ar + p * AROWS;
            As[ak+0][r] = pa[p].x; As[ak+1][r] = pa[p].y;
            As[ak+2][r] = pa[p].z; As[ak+3][r] = pa[p].w;
        }
#pragma unroll
        for (int p = 0; p < WV; p++) {
            int r = ar + p * AROWS;
            Ws[ak+0][r] = pw[p].x; Ws[ak+1][r] = pw[p].y;
            Ws[ak+2][r] = pw[p].z; Ws[ak+3][r] = pw[p].w;
        }
        __syncthreads();

        if (k0 + BK < K) {
#pragma unroll
            for (int p = 0; p < AV; p++)
                pa[p] = *(const float4*)(Ag + (k0 + BK) + (size_t)p * AROWS * lda);
#pragma unroll
            for (int p = 0; p < WV; p++)
                pw[p] = (n0 + ar + p * AROWS < N)
                      ? *(const float4*)(Wg + (k0 + BK) + (size_t)p * AROWS * ldw)
                      : make_float4(0.f, 0.f, 0.f, 0.f);
        }

#pragma unroll
        for (int k = 0; k < BK; k++) {
            float a[TM];
#pragma unroll
            for (int i = 0; i < TM; i += 4)
                *(float4*)(a + i) = *(const float4*)(&As[k][ty * TM + i]);
            u64 w2[TN/2];
#pragma unroll
            for (int j = 0; j < TN; j += 4) {
                ulonglong2 wv = *(const ulonglong2*)(&Ws[k][tx * TN + j]);
                w2[j/2] = wv.x; w2[j/2 + 1] = wv.y;
            }
#pragma unroll
            for (int i = 0; i < TM; i++) {
                u64 ad = dup2(a[i]);
#pragma unroll
                for (int j = 0; j < TN/2; j++)
                    acc[i][j] = ffma2(ad, w2[j], acc[i][j]);
            }
        }
        __syncthreads();
    }

#pragma unroll
    for (int i = 0; i < TM; i++) {
        float* crow = C + (size_t)(m0 + ty * TM + i) * ldc;
#pragma unroll
        for (int j = 0; j < TN; j += 4) {
            int n = n0 + tx * TN + j;
            if (n + 3 < N) {
                float2 p0 = unpack2(acc[i][j/2]);
                float2 p1 = unpack2(acc[i][j/2 + 1]);
                float4 v = make_float4(p0.x, p0.y, p1.x, p1.y);
                if (EPI == 1) {
                    v.x = softplusf(v.x + bias[n+0]);
                    v.y = softplusf(v.y + bias[n+1]);
                    v.z = softplusf(v.z + bias[n+2]);
                    v.w = softplusf(v.w + bias[n+3]);
                }
                *(float4*)(crow + n) = v;
            }
        }
    }
}

// ---------------------------------------------------------------------------
// Causal depthwise conv (width 4) + SiLU
// ---------------------------------------------------------------------------
__global__ void conv_silu_kernel(const float* __restrict__ cw,
                                 const float* __restrict__ cb) {
    int idx = blockIdx.x * blockDim.x + threadIdx.x;
    if (idx >= NTOK * DINNER) return;
    int ch = idx % DINNER;
    int t  = idx / DINNER;
    int l  = t % SEQ;
    float acc = cb[ch];
#pragma unroll
    for (int k = 0; k < DCONV; k++) {
        int dl = l + k - (DCONV - 1);
        if (dl >= 0)
            acc = fmaf(g_xz[(size_t)(t + k - (DCONV - 1)) * (2*DINNER) + ch],
                       cw[ch * DCONV + k], acc);
    }
    g_xssm[idx] = siluf(acc);
}

// ---------------------------------------------------------------------------
// Selective scan: 4 threads/channel, 4 states each, shfl-reduce y
// ---------------------------------------------------------------------------
__global__ void scan_kernel(const float* __restrict__ A_log_l,
                            const float* __restrict__ Dp_l) {
    int lane = threadIdx.x;
    int gch = blockIdx.x * 16 + (lane >> 2);
    int sg  = lane & 3;
    int b   = gch / DINNER;
    int ch  = gch - b * DINNER;
    int s0  = sg * 4;

    float A0 = -__expf(A_log_l[ch * DSTATE + s0 + 0]);
    float A1 = -__expf(A_log_l[ch * DSTATE + s0 + 1]);
    float A2 = -__expf(A_log_l[ch * DSTATE + s0 + 2]);
    float A3 = -__expf(A_log_l[ch * DSTATE + s0 + 3]);
    float Dpc = Dp_l[ch];

    const float* dtp = g_dt   + (size_t)b * SEQ * DINNER + ch;
    const float* xp  = g_xssm + (size_t)b * SEQ * DINNER + ch;
    const float* blp = g_dbl  + (size_t)b * SEQ * DBLW + DTRANK + s0;
    float*       gp  = g_gate + (size_t)b * SEQ * DINNER + ch;

    float h0 = 0.f, h1 = 0.f, h2 = 0.f, h3 = 0.f;
    float dtv = *dtp, xv = *xp;
    float4 Bv = *(const float4*)blp;
    float4 Cv = *(const float4*)(blp + DSTATE);

    for (int t = 0; t < SEQ; t++) {
        bool more = (t + 1 < SEQ);
        float ndt = more ? dtp[DINNER] : 0.f;
        float nxv = more ? xp[DINNER]  : 0.f;
        float4 nB = more ? *(const float4*)(blp + DBLW)          : make_float4(0,0,0,0);
        float4 nC = more ? *(const float4*)(blp + DBLW + DSTATE) : make_float4(0,0,0,0);

        float dx = dtv * xv;
        float e0 = fexp(dtv * A0);
        float e1 = fexp(dtv * A1);
        float e2 = fexp(dtv * A2);
        float e3 = fexp(dtv * A3);
        h0 = fmaf(h0, e0, dx * Bv.x);
        h1 = fmaf(h1, e1, dx * Bv.y);
        h2 = fmaf(h2, e2, dx * Bv.z);
        h3 = fmaf(h3, e3, dx * Bv.w);
        float y = fmaf(h0, Cv.x, fmaf(h1, Cv.y, fmaf(h2, Cv.z, h3 * Cv.w)));
        y += __shfl_xor_sync(0xffffffffu, y, 1);
        y += __shfl_xor_sync(0xffffffffu, y, 2);
        if (sg == 0) *gp = fmaf(xv, Dpc, y);

        dtv = ndt; xv = nxv; Bv = nB; Cv = nC;
        dtp += DINNER; xp += DINNER; blp += DBLW; gp += DINNER;
    }
}

__global__ void gate_kernel() {
    int idx = blockIdx.x * blockDim.x + threadIdx.x;
    if (idx >= NTOK * DINNER) return;
    int ch = idx % DINNER;
    int t  = idx / DINNER;
    float z = g_xz[(size_t)t * (2*DINNER) + DINNER + ch];
    g_gate[idx] *= siluf(z);
}

__global__ void ln_kernel(const float* __restrict__ gw,
                          const float* __restrict__ bw) {
    __shared__ float red[64];
    int row = blockIdx.x;
    const float* xr = g_x + (size_t)row * DIM;
    float s = 0.f, s2 = 0.f;
    for (int i = threadIdx.x; i < DIM; i += blockDim.x) {
        float v = xr[i]; s += v; s2 = fmaf(v, v, s2);
    }
#pragma unroll
    for (int off = 16; off; off >>= 1) {
        s  += __shfl_xor_sync(0xffffffffu, s,  off);
        s2 += __shfl_xor_sync(0xffffffffu, s2, off);
    }
    int w = threadIdx.x >> 5;
    if ((threadIdx.x & 31) == 0) { red[w] = s; red[w + 32] = s2; }
    __syncthreads();
    if (threadIdx.x < 32) {
        int nw = blockDim.x >> 5;
        s  = (threadIdx.x < nw) ? red[threadIdx.x]      : 0.f;
        s2 = (threadIdx.x < nw) ? red[threadIdx.x + 32] : 0.f;
#pragma unroll
        for (int off = 4; off; off >>= 1) {
            s  += __shfl_xor_sync(0xffffffffu, s,  off);
            s2 += __shfl_xor_sync(0xffffffffu, s2, off);
        }
        if (threadIdx.x == 0) { red[0] = s; red[1] = s2; }
    }
    __syncthreads();
    float mu  = red[0] * (1.f / DIM);
    float var = red[1] * (1.f / DIM) - mu * mu;
    float rs  = rsqrtf(var + EPS);
    for (int i = threadIdx.x; i < DIM; i += blockDim.x)
        g_ln[(size_t)row * DIM + i] = (xr[i] - mu) * rs * gw[i] + bw[i];
}

// ---------------------------------------------------------------------------
// Launch sequence
// ---------------------------------------------------------------------------
extern "C" void kernel_launch(void* const* d_in, const int* in_sizes, int n_in,
                              void* d_out, int out_size) {
    (void)in_sizes; (void)n_in; (void)out_size;

    const int*   ids    = (const int*)  d_in[0];
    const float* emb    = (const float*)d_in[1];
    const float* W_in   = (const float*)d_in[2];
    const float* conv_w = (const float*)d_in[3];
    const float* conv_b = (const float*)d_in[4];
    const float* W_x    = (const float*)d_in[5];
    const float* W_dt   = (const float*)d_in[6];
    const float* b_dt   = (const float*)d_in[7];
    const float* A_log  = (const float*)d_in[8];
    const float* Dp     = (const float*)d_in[9];
    const float* W_out  = (const float*)d_in[10];
    const float* ln_g   = (const float*)d_in[11];
    const float* ln_b   = (const float*)d_in[12];
    const float* W_head = (const float*)d_in[13];
    float* out = (float*)d_out;

    float *px, *pxz, *pxssm, *pdbl, *pdt, *pgate, *pln;
    cudaGetSymbolAddress((void**)&px,    g_x);
    cudaGetSymbolAddress((void**)&pxz,   g_xz);
    cudaGetSymbolAddress((void**)&pxssm, g_xssm);
    cudaGetSymbolAddress((void**)&pdbl,  g_dbl);
    cudaGetSymbolAddress((void**)&pdt,   g_dt);
    cudaGetSymbolAddress((void**)&pgate, g_gate);
    cudaGetSymbolAddress((void**)&pln,   g_ln);

    embed_kernel<<<NTOK, DIM/4>>>(ids, emb);

    const int EW = (NTOK * DINNER + 255) / 256;

    for (int i = 0; i < DEPTH; i++) {
        const float* Wi  = W_in   + (size_t)i * 2*DINNER*DIM;
        const float* cwi = conv_w + (size_t)i * DINNER*DCONV;
        const float* cbi = conv_b + (size_t)i * DINNER;
        const float* Wxi = W_x    + (size_t)i * DBLW*DINNER;
        const float* Wdi = W_dt   + (size_t)i * DINNER*DTRANK;
        const float* bdi = b_dt   + (size_t)i * DINNER;
        const float* Ali = A_log  + (size_t)i * DINNER*DSTATE;
        const float* Dpi = Dp     + (size_t)i * DINNER;
        const float* Woi = W_out  + (size_t)i * DIM*DINNER;

        // xz = x @ W_in^T : [4096, 3072]  (tensor core tf32)
        gemm_wmma<<<dim3(2*DINNER/128, NTOK/128), 256>>>(
            px, DIM, Wi, DIM, pxz, 2*DINNER, DIM);

        conv_silu_kernel<<<EW, 256>>>(cwi, cbi);

        // dbl = x_ssm @ W_x^T : [4096, 80]  (SIMT, ragged N)
        gemm_nt<0><<<dim3(1, NTOK/128), 256>>>(
            pxssm, DINNER, Wxi, DINNER, nullptr, pdbl, DBLW, DBLW, DINNER);

        // dt = softplus(dbl[:, :48] @ W_dt^T + b_dt)  (SIMT, K=48)
        gemm_nt<1><<<dim3(DINNER/128, NTOK/128), 256>>>(
            pdbl, DBLW, Wdi, DTRANK, bdi, pdt, DINNER, DINNER, DTRANK);

        scan_kernel<<<(BATCH*DINNER)/16, 64>>>(Ali, Dpi);

        gate_kernel<<<EW, 256>>>();

        // x = g @ W_out^T : [4096, 768]  (tensor core tf32)
        gemm_wmma<<<dim3(DIM/128, NTOK/128), 256>>>(
            pgate, DINNER, Woi, DINNER, px, DIM, DINNER);
    }

    ln_kernel<<<NTOK, 256>>>(ln_g, ln_b);

    // logits = ln @ W_head^T : [4096, 32000]  (tensor core tf32)
    gemm_wmma<<<dim3(VOCAB/128, NTOK/128), 256>>>(
        pln, DIM, W_head, DIM, out, VOCAB, DIM);
}